// round 14
// baseline (speedup 1.0000x reference)
#include <cuda_runtime.h>
#include <cuda_bf16.h>
#include <math.h>
#include <stdint.h>

// Problem constants
#define BB 2
#define SS 2048
#define DM 2048
#define HH 16
#define DH 128
#define NBH (BB*HH)
#define MROWS (BB*SS)        // 4096

// ---------------- scratch ------------------------------------------------------
__device__ float g_q[MROWS * DM];                  // (B,S,H,DH)
__device__ float g_k[MROWS * DM];
__device__ float g_v[(size_t)BB * HH * DH * SS];   // V transposed: (B,H,DH,S)
__device__ float g_ao[MROWS * DM];                 // attention out (B,S,H*DH)

// ---------------- helpers ------------------------------------------------------
__device__ __forceinline__ void split2(float a, float b, uint32_t& hi, uint32_t& lo) {
    __nv_bfloat16 ha = __float2bfloat16_rn(a);
    __nv_bfloat16 hb = __float2bfloat16_rn(b);
    __nv_bfloat16 la = __float2bfloat16_rn(a - __bfloat162float(ha));
    __nv_bfloat16 lb = __float2bfloat16_rn(b - __bfloat162float(hb));
    __nv_bfloat162 h2 = __halves2bfloat162(ha, hb);
    __nv_bfloat162 l2 = __halves2bfloat162(la, lb);
    hi = *reinterpret_cast<uint32_t*>(&h2);
    lo = *reinterpret_cast<uint32_t*>(&l2);
}

__device__ __forceinline__ void mma_bf16(float c[4],
    uint32_t a0, uint32_t a1, uint32_t a2, uint32_t a3,
    uint32_t b0, uint32_t b1)
{
    asm volatile(
        "mma.sync.aligned.m16n8k16.row.col.f32.bf16.bf16.f32 "
        "{%0,%1,%2,%3},{%4,%5,%6,%7},{%8,%9},{%0,%1,%2,%3};"
        : "+f"(c[0]), "+f"(c[1]), "+f"(c[2]), "+f"(c[3])
        : "r"(a0), "r"(a1), "r"(a2), "r"(a3), "r"(b0), "r"(b1));
}

// ---------------- GEMM core: 512 threads, 128x128x32 tile ----------------------
// A [M,K], B [N,K] fp32 row-major; split to bf16 hi/lo in smem; 3-term product.
// 16 warps (4m x 4n); each warp 32x32 (2 m-frags x 4 n-frags).
// Per-output-element MMA order identical to the 256-thread version.
#define TBM 128
#define TBN 128
#define TBK 32
#define SAS 40   // bf16 row stride (32 + 8 pad)

__device__ __forceinline__ void gemm_core(
    const float* __restrict__ A, const float* __restrict__ B,
    int K, int lda, int ldb, int row0, int col0, float acc[2][4][4])
{
    __shared__ __nv_bfloat16 sAh[TBM * SAS];
    __shared__ __nv_bfloat16 sAl[TBM * SAS];
    __shared__ __nv_bfloat16 sBh[TBN * SAS];
    __shared__ __nv_bfloat16 sBl[TBN * SAS];

    const int tid  = threadIdx.x;          // 0..511
    const int lane = tid & 31;
    const int wm   = (tid >> 5) & 3;       // 0..3
    const int wn   = tid >> 7;             // 0..3

    // staging: 128 rows x 32 k fp32 each matrix; 512 thr -> 2 float4 per matrix
    const int ar = tid >> 3;               // 0..63 (+64*r)
    const int ac = (tid & 7) * 4;

    float4 ra[2], rb[2];

    auto load_tile = [&](int k0) {
        #pragma unroll
        for (int r = 0; r < 2; r++) {
            ra[r] = *reinterpret_cast<const float4*>(
                &A[(size_t)(row0 + ar + 64 * r) * lda + k0 + ac]);
            rb[r] = *reinterpret_cast<const float4*>(
                &B[(size_t)(col0 + ar + 64 * r) * ldb + k0 + ac]);
        }
    };

    auto store_tile = [&]() {
        #pragma unroll
        for (int r = 0; r < 2; r++) {
            const int off = (ar + 64 * r) * SAS + ac;
            uint32_t h0, l0, h1, l1;
            split2(ra[r].x, ra[r].y, h0, l0);
            split2(ra[r].z, ra[r].w, h1, l1);
            *reinterpret_cast<uint32_t*>(&sAh[off])     = h0;
            *reinterpret_cast<uint32_t*>(&sAh[off + 2]) = h1;
            *reinterpret_cast<uint32_t*>(&sAl[off])     = l0;
            *reinterpret_cast<uint32_t*>(&sAl[off + 2]) = l1;
            split2(rb[r].x, rb[r].y, h0, l0);
            split2(rb[r].z, rb[r].w, h1, l1);
            *reinterpret_cast<uint32_t*>(&sBh[off])     = h0;
            *reinterpret_cast<uint32_t*>(&sBh[off + 2]) = h1;
            *reinterpret_cast<uint32_t*>(&sBl[off])     = l0;
            *reinterpret_cast<uint32_t*>(&sBl[off + 2]) = l1;
        }
    };

    load_tile(0);
    store_tile();
    __syncthreads();

    for (int k0 = 0; k0 < K; k0 += TBK) {
        const bool more = (k0 + TBK) < K;
        if (more) load_tile(k0 + TBK);

        #pragma unroll
        for (int kk = 0; kk < 2; kk++) {
            const int kb = kk * 16 + (lane & 3) * 2;
            uint32_t ah[2][4], al[2][4];
            #pragma unroll
            for (int i = 0; i < 2; i++) {
                const int m = wm * 32 + i * 16 + (lane >> 2);
                ah[i][0] = *reinterpret_cast<const uint32_t*>(&sAh[m * SAS + kb]);
                ah[i][1] = *reinterpret_cast<const uint32_t*>(&sAh[(m + 8) * SAS + kb]);
                ah[i][2] = *reinterpret_cast<const uint32_t*>(&sAh[m * SAS + kb + 8]);
                ah[i][3] = *reinterpret_cast<const uint32_t*>(&sAh[(m + 8) * SAS + kb + 8]);
                al[i][0] = *reinterpret_cast<const uint32_t*>(&sAl[m * SAS + kb]);
                al[i][1] = *reinterpret_cast<const uint32_t*>(&sAl[(m + 8) * SAS + kb]);
                al[i][2] = *reinterpret_cast<const uint32_t*>(&sAl[m * SAS + kb + 8]);
                al[i][3] = *reinterpret_cast<const uint32_t*>(&sAl[(m + 8) * SAS + kb + 8]);
            }
            uint32_t bh[4][2], bl[4][2];
            #pragma unroll
            for (int j = 0; j < 4; j++) {
                const int n = wn * 32 + j * 8 + (lane >> 2);
                bh[j][0] = *reinterpret_cast<const uint32_t*>(&sBh[n * SAS + kb]);
                bh[j][1] = *reinterpret_cast<const uint32_t*>(&sBh[n * SAS + kb + 8]);
                bl[j][0] = *reinterpret_cast<const uint32_t*>(&sBl[n * SAS + kb]);
                bl[j][1] = *reinterpret_cast<const uint32_t*>(&sBl[n * SAS + kb + 8]);
            }
            #pragma unroll
            for (int i = 0; i < 2; i++)
                #pragma unroll
                for (int j = 0; j < 4; j++) {
                    mma_bf16(acc[i][j], ah[i][0], ah[i][1], ah[i][2], ah[i][3],
                             bh[j][0], bh[j][1]);
                    mma_bf16(acc[i][j], ah[i][0], ah[i][1], ah[i][2], ah[i][3],
                             bl[j][0], bl[j][1]);
                    mma_bf16(acc[i][j], al[i][0], al[i][1], al[i][2], al[i][3],
                             bh[j][0], bh[j][1]);
                }
        }
        __syncthreads();
        if (more) {
            store_tile();
            __syncthreads();
        }
    }
}

// ---------------- fused QKV projection: one launch, z selects weight -----------
__global__ void __launch_bounds__(512) qkv_gemm(
    const float* __restrict__ x,
    const float* __restrict__ wq, const float* __restrict__ wk,
    const float* __restrict__ wv,
    float* __restrict__ q, float* __restrict__ k, float* __restrict__ vt)
{
    const int z = blockIdx.z;
    const float* B = (z == 0) ? wq : (z == 1) ? wk : wv;
    const int row0 = blockIdx.y * TBM;
    const int col0 = blockIdx.x * TBN;

    float acc[2][4][4] = {};
    gemm_core(x, B, DM, DM, DM, row0, col0, acc);

    const int lane = threadIdx.x & 31;
    const int wm   = (threadIdx.x >> 5) & 3;
    const int wn   = threadIdx.x >> 7;

    if (z == 2) {
        const int b = row0 / SS;
        float* vp = vt + ((size_t)(b * HH + blockIdx.x) * DH) * SS;
        #pragma unroll
        for (int i = 0; i < 2; i++) {
            const int s = (row0 - b * SS) + wm * 32 + i * 16 + (lane >> 2);
            #pragma unroll
            for (int j = 0; j < 4; j++) {
                const int d = wn * 32 + j * 8 + 2 * (lane & 3);
                vp[(size_t)d * SS + s]           = acc[i][j][0];
                vp[(size_t)(d + 1) * SS + s]     = acc[i][j][1];
                vp[(size_t)d * SS + s + 8]       = acc[i][j][2];
                vp[(size_t)(d + 1) * SS + s + 8] = acc[i][j][3];
            }
        }
    } else {
        float* C = (z == 0) ? q : k;
        #pragma unroll
        for (int i = 0; i < 2; i++) {
            const int r = row0 + wm * 32 + i * 16 + (lane >> 2);
            #pragma unroll
            for (int j = 0; j < 4; j++) {
                const int cc = col0 + wn * 32 + j * 8 + 2 * (lane & 3);
                float2 lo = make_float2(acc[i][j][0], acc[i][j][1]);
                float2 hi = make_float2(acc[i][j][2], acc[i][j][3]);
                *reinterpret_cast<float2*>(&C[(size_t)r * DM + cc]) = lo;
                *reinterpret_cast<float2*>(&C[(size_t)(r + 8) * DM + cc]) = hi;
            }
        }
    }
}

// ---------------- output projection: out = ao @ wo^T ---------------------------
__global__ void __launch_bounds__(512) wo_gemm(
    const float* __restrict__ ao, const float* __restrict__ wo,
    float* __restrict__ out)
{
    const int row0 = blockIdx.y * TBM;
    const int col0 = blockIdx.x * TBN;

    float acc[2][4][4] = {};
    gemm_core(ao, wo, DM, DM, DM, row0, col0, acc);

    const int lane = threadIdx.x & 31;
    const int wm   = (threadIdx.x >> 5) & 3;
    const int wn   = threadIdx.x >> 7;

    #pragma unroll
    for (int i = 0; i < 2; i++) {
        const int r = row0 + wm * 32 + i * 16 + (lane >> 2);
        #pragma unroll
        for (int j = 0; j < 4; j++) {
            const int cc = col0 + wn * 32 + j * 8 + 2 * (lane & 3);
            float2 lo = make_float2(acc[i][j][0], acc[i][j][1]);
            float2 hi = make_float2(acc[i][j][2], acc[i][j][3]);
            *reinterpret_cast<float2*>(&out[(size_t)r * DM + cc]) = lo;
            *reinterpret_cast<float2*>(&out[(size_t)(r + 8) * DM + cc]) = hi;
        }
    }
}

// ---------------- RMSNorm + RoPE: merged q+k, 4 heads per block ----------------
__global__ void __launch_bounds__(256) rmsnorm_rope_kernel(
    float* __restrict__ qt, float* __restrict__ kt,
    const float* __restrict__ qw, const float* __restrict__ kw,
    const float* __restrict__ freqs)
{
    float* t       = blockIdx.y ? kt : qt;
    const float* w = blockIdx.y ? kw : qw;

    const int grp = threadIdx.x >> 6;        // 0..3
    const int i   = threadIdx.x & 63;        // 0..63
    const int idx = blockIdx.x * 4 + grp;    // b*S*H + s*H + h
    const int s   = (idx / HH) % SS;
    float* v = t + (size_t)idx * DH;

    float x0 = v[i];
    float x1 = v[i + 64];
    float ss = x0 * x0 + x1 * x1;
    #pragma unroll
    for (int o = 16; o > 0; o >>= 1) ss += __shfl_xor_sync(0xffffffffu, ss, o);
    __shared__ float sm[8];
    if ((i & 31) == 0) sm[threadIdx.x >> 5] = ss;
    __syncthreads();
    float total = sm[grp * 2] + sm[grp * 2 + 1];
    float r = rsqrtf(total * (1.0f / 128.0f) + 1e-6f);

    float n0 = x0 * r * w[i];
    float n1 = x1 * r * w[i + 64];

    const float* F = freqs + (size_t)s * 256 + i * 4;
    v[i]      = F[0] * n0 + F[1] * n1;
    v[i + 64] = F[2] * n0 + F[3] * n1;
}

// ---------------- Flash attention (R7, unchanged) ------------------------------
#define FKV 64
#define KST 136
#define VST 72

__global__ void __launch_bounds__(256) flash_kernel(
    const float* __restrict__ q, const float* __restrict__ k,
    const float* __restrict__ vt, float* __restrict__ ao)
{
    extern __shared__ __nv_bfloat16 fsm[];
    __nv_bfloat16* Kh = fsm;
    __nv_bfloat16* Kl = Kh + FKV * KST;
    __nv_bfloat16* Vh = Kl + FKV * KST;
    __nv_bfloat16* Vl = Vh + DH * VST;

    const int tid  = threadIdx.x;
    const int lane = tid & 31;
    const int w    = tid >> 5;
    const int g    = lane >> 2;
    const int t    = lane & 3;
    const int bh   = blockIdx.y;
    const int b    = bh >> 4;
    const int h    = bh & 15;
    const int q0   = blockIdx.x * 128;

    const float* qb  = q  + ((size_t)(b * SS + q0)) * DM + h * DH;
    const float* kb  = k  + (size_t)b * SS * DM + h * DH;
    const float* vb  = vt + (size_t)bh * DH * SS;
    float*       aob = ao + ((size_t)(b * SS + q0)) * DM + h * DH;

    const float scale = 0.08838834764831845f;

    uint32_t qh[8][4], ql[8][4];
    {
        const float* qw = qb + (size_t)(w * 16) * DM;
        #pragma unroll
        for (int kc = 0; kc < 8; kc++) {
            #pragma unroll
            for (int e = 0; e < 4; e++) {
                const int r = g + ((e & 1) ? 8 : 0);
                const int c = kc * 16 + 2 * t + ((e & 2) ? 8 : 0);
                float2 v2 = *reinterpret_cast<const float2*>(&qw[(size_t)r * DM + c]);
                split2(v2.x * scale, v2.y * scale, qh[kc][e], ql[kc][e]);
            }
        }
    }

    float oacc[16][4] = {};
    float m0 = -INFINITY, m1 = -INFINITY, l0 = 0.0f, l1 = 0.0f;

    for (int kv0 = 0; kv0 < SS; kv0 += FKV) {
        __syncthreads();
        {
            const int row = tid >> 3;
            const int cb  = (tid & 7) * 4;
            #pragma unroll
            for (int pr = 0; pr < 2; pr++) {
                const float* src = kb + (size_t)(kv0 + row + 32 * pr) * DM;
                #pragma unroll
                for (int pc = 0; pc < 4; pc++) {
                    const int c = cb + 32 * pc;
                    float4 v4 = *reinterpret_cast<const float4*>(&src[c]);
                    uint32_t h0, lo0, h1, lo1;
                    split2(v4.x, v4.y, h0, lo0);
                    split2(v4.z, v4.w, h1, lo1);
                    const int off = (row + 32 * pr) * KST + c;
                    *reinterpret_cast<uint32_t*>(&Kh[off])     = h0;
                    *reinterpret_cast<uint32_t*>(&Kh[off + 2]) = h1;
                    *reinterpret_cast<uint32_t*>(&Kl[off])     = lo0;
                    *reinterpret_cast<uint32_t*>(&Kl[off + 2]) = lo1;
                }
            }
        }
        {
            const int row = tid >> 3;
            const int cb  = (tid & 7) * 4;
            #pragma unroll
            for (int pr = 0; pr < 4; pr++) {
                const float* src = vb + (size_t)(row + 32 * pr) * SS + kv0;
                #pragma unroll
                for (int pc = 0; pc < 2; pc++) {
                    const int c = cb + 32 * pc;
                    float4 v4 = *reinterpret_cast<const float4*>(&src[c]);
                    uint32_t h0, lo0, h1, lo1;
                    split2(v4.x, v4.y, h0, lo0);
                    split2(v4.z, v4.w, h1, lo1);
                    const int off = (row + 32 * pr) * VST + c;
                    *reinterpret_cast<uint32_t*>(&Vh[off])     = h0;
                    *reinterpret_cast<uint32_t*>(&Vh[off + 2]) = h1;
                    *reinterpret_cast<uint32_t*>(&Vl[off])     = lo0;
                    *reinterpret_cast<uint32_t*>(&Vl[off + 2]) = lo1;
                }
            }
        }
        __syncthreads();

        float sacc[8][4] = {};
        #pragma unroll
        for (int j = 0; j < 8; j++) {
            #pragma unroll
            for (int kc = 0; kc < 8; kc++) {
                const int off = (j * 8 + g) * KST + kc * 16 + 2 * t;
                uint32_t bh0 = *reinterpret_cast<const uint32_t*>(&Kh[off]);
                uint32_t bh1 = *reinterpret_cast<const uint32_t*>(&Kh[off + 8]);
                uint32_t bl0 = *reinterpret_cast<const uint32_t*>(&Kl[off]);
                uint32_t bl1 = *reinterpret_cast<const uint32_t*>(&Kl[off + 8]);
                mma_bf16(sacc[j], qh[kc][0], qh[kc][1], qh[kc][2], qh[kc][3], bh0, bh1);
                mma_bf16(sacc[j], qh[kc][0], qh[kc][1], qh[kc][2], qh[kc][3], bl0, bl1);
                mma_bf16(sacc[j], ql[kc][0], ql[kc][1], ql[kc][2], ql[kc][3], bh0, bh1);
            }
        }

        float mx0 = -INFINITY, mx1 = -INFINITY;
        #pragma unroll
        for (int j = 0; j < 8; j++) {
            mx0 = fmaxf(mx0, fmaxf(sacc[j][0], sacc[j][1]));
            mx1 = fmaxf(mx1, fmaxf(sacc[j][2], sacc[j][3]));
        }
        mx0 = fmaxf(mx0, __shfl_xor_sync(0xffffffffu, mx0, 1));
        mx0 = fmaxf(mx0, __shfl_xor_sync(0xffffffffu, mx0, 2));
        mx1 = fmaxf(mx1, __shfl_xor_sync(0xffffffffu, mx1, 1));
        mx1 = fmaxf(mx1, __shfl_xor_sync(0xffffffffu, mx1, 2));

        const float nm0 = fmaxf(m0, mx0), nm1 = fmaxf(m1, mx1);
        const float al0 = __expf(m0 - nm0), al1 = __expf(m1 - nm1);
        m0 = nm0; m1 = nm1;

        float s0 = 0.0f, s1 = 0.0f;
        #pragma unroll
        for (int j = 0; j < 8; j++) {
            sacc[j][0] = __expf(sacc[j][0] - nm0);
            sacc[j][1] = __expf(sacc[j][1] - nm0);
            sacc[j][2] = __expf(sacc[j][2] - nm1);
            sacc[j][3] = __expf(sacc[j][3] - nm1);
            s0 += sacc[j][0] + sacc[j][1];
            s1 += sacc[j][2] + sacc[j][3];
        }
        s0 += __shfl_xor_sync(0xffffffffu, s0, 1);
        s0 += __shfl_xor_sync(0xffffffffu, s0, 2);
        s1 += __shfl_xor_sync(0xffffffffu, s1, 1);
        s1 += __shfl_xor_sync(0xffffffffu, s1, 2);
        l0 = l0 * al0 + s0;
        l1 = l1 * al1 + s1;

        #pragma unroll
        for (int jn = 0; jn < 16; jn++) {
            oacc[jn][0] *= al0; oacc[jn][1] *= al0;
            oacc[jn][2] *= al1; oacc[jn][3] *= al1;
        }

        #pragma unroll
        for (int kc2 = 0; kc2 < 4; kc2++) {
            const int j0 = 2 * kc2, j1 = 2 * kc2 + 1;
            uint32_t pa0h, pa0l, pa1h, pa1l, pa2h, pa2l, pa3h, pa3l;
            split2(sacc[j0][0], sacc[j0][1], pa0h, pa0l);
            split2(sacc[j0][2], sacc[j0][3], pa1h, pa1l);
            split2(sacc[j1][0], sacc[j1][1], pa2h, pa2l);
            split2(sacc[j1][2], sacc[j1][3], pa3h, pa3l);
            #pragma unroll
            for (int jn = 0; jn < 16; jn++) {
                const int off = (jn * 8 + g) * VST + kc2 * 16 + 2 * t;
                uint32_t bh0 = *reinterpret_cast<const uint32_t*>(&Vh[off]);
                uint32_t bh1 = *reinterpret_cast<const uint32_t*>(&Vh[off + 8]);
                uint32_t bl0 = *reinterpret_cast<const uint32_t*>(&Vl[off]);
                uint32_t bl1 = *reinterpret_cast<const uint32_t*>(&Vl[off + 8]);
                mma_bf16(oacc[jn], pa0h, pa1h, pa2h, pa3h, bh0, bh1);
                mma_bf16(oacc[jn], pa0h, pa1h, pa2h, pa3h, bl0, bl1);
                mma_bf16(oacc[jn], pa0l, pa1l, pa2l, pa3l, bh0, bh1);
            }
        }
    }

    const float inv0 = 1.0f / l0, inv1 = 1.0f / l1;
    #pragma unroll
    for (int jn = 0; jn < 16; jn++) {
        const int r = w * 16 + g;
        const int c = jn * 8 + 2 * t;
        float2 lo = make_float2(oacc[jn][0] * inv0, oacc[jn][1] * inv0);
        float2 hi = make_float2(oacc[jn][2] * inv1, oacc[jn][3] * inv1);
        *reinterpret_cast<float2*>(&aob[(size_t)r * DM + c])       = lo;
        *reinterpret_cast<float2*>(&aob[(size_t)(r + 8) * DM + c]) = hi;
    }
}

// ---------------- launch -------------------------------------------------------
extern "C" void kernel_launch(void* const* d_in, const int* in_sizes, int n_in,
                              void* d_out, int out_size)
{
    const float* x     = (const float*)d_in[0];
    const float* rope  = (const float*)d_in[1];
    const float* wq    = (const float*)d_in[2];
    const float* wk    = (const float*)d_in[3];
    const float* wv    = (const float*)d_in[4];
    const float* wo    = (const float*)d_in[5];
    const float* qnw   = (const float*)d_in[6];
    const float* knw   = (const float*)d_in[7];
    float* out = (float*)d_out;

    float *q, *k, *vt, *ao;
    cudaGetSymbolAddress((void**)&q,  g_q);
    cudaGetSymbolAddress((void**)&k,  g_k);
    cudaGetSymbolAddress((void**)&vt, g_v);
    cudaGetSymbolAddress((void**)&ao, g_ao);

    cudaFuncSetAttribute(flash_kernel, cudaFuncAttributeMaxDynamicSharedMemorySize, 71680);

    // ---- QKV projections: ONE launch, z selects weight/output ----------------
    qkv_gemm<<<dim3(DM / TBN, MROWS / TBM, 3), 512>>>(x, wq, wk, wv, q, k, vt);

    // ---- RMSNorm + RoPE on q and k: one merged launch -------------------------
    rmsnorm_rope_kernel<<<dim3(MROWS * HH / 4, 2), 256>>>(q, k, qnw, knw, rope);

    // ---- fused attention ------------------------------------------------------
    flash_kernel<<<dim3(SS / 128, NBH), 256, 71680>>>(q, k, vt, ao);

    // ---- output projection ----------------------------------------------------
    wo_gemm<<<dim3(DM / TBN, MROWS / TBM), 512>>>(ao, wo, out);
}

// round 17
// speedup vs baseline: 1.1019x; 1.1019x over previous
#include <cuda_runtime.h>
#include <cuda_bf16.h>
#include <math.h>
#include <stdint.h>

// Problem constants
#define BB 2
#define SS 2048
#define DM 2048
#define HH 16
#define DH 128
#define NBH (BB*HH)
#define MROWS (BB*SS)        // 4096

// ---------------- scratch ------------------------------------------------------
__device__ float g_q[MROWS * DM];                  // (B,S,H,DH)
__device__ float g_k[MROWS * DM];
__device__ float g_v[(size_t)BB * HH * DH * SS];   // V transposed: (B,H,DH,S)
__device__ float g_ao[MROWS * DM];                 // attention out (B,S,H*DH)

// ---------------- helpers ------------------------------------------------------
__device__ __forceinline__ void split2(float a, float b, uint32_t& hi, uint32_t& lo) {
    __nv_bfloat16 ha = __float2bfloat16_rn(a);
    __nv_bfloat16 hb = __float2bfloat16_rn(b);
    __nv_bfloat16 la = __float2bfloat16_rn(a - __bfloat162float(ha));
    __nv_bfloat16 lb = __float2bfloat16_rn(b - __bfloat162float(hb));
    __nv_bfloat162 h2 = __halves2bfloat162(ha, hb);
    __nv_bfloat162 l2 = __halves2bfloat162(la, lb);
    hi = *reinterpret_cast<uint32_t*>(&h2);
    lo = *reinterpret_cast<uint32_t*>(&l2);
}

__device__ __forceinline__ void mma_bf16(float c[4],
    uint32_t a0, uint32_t a1, uint32_t a2, uint32_t a3,
    uint32_t b0, uint32_t b1)
{
    asm volatile(
        "mma.sync.aligned.m16n8k16.row.col.f32.bf16.bf16.f32 "
        "{%0,%1,%2,%3},{%4,%5,%6,%7},{%8,%9},{%0,%1,%2,%3};"
        : "+f"(c[0]), "+f"(c[1]), "+f"(c[2]), "+f"(c[3])
        : "r"(a0), "r"(a1), "r"(a2), "r"(a3), "r"(b0), "r"(b1));
}

// ---------------- GEMM core: 256 threads, CTA 128x256, warp tile 64x64 ---------
// A [M,K], B [N,K] fp32 row-major; split to bf16 hi/lo in smem; 3-term product.
// 8 warps (2m x 4n); each warp 64x64 (4 m-frags x 8 n-frags).
// Per-output-element k/3-term accumulation order identical to R7/R13.
#define TBM 128
#define TBN 256
#define TBK 32
#define SAS 40   // bf16 row stride (32 + 8 pad)
#define SM_AH 0
#define SM_AL (TBM * SAS)
#define SM_BH (2 * TBM * SAS)
#define SM_BL (2 * TBM * SAS + TBN * SAS)
#define GEMM_SMEM ((2 * TBM * SAS + 2 * TBN * SAS) * 2)   // 61440 bytes

__device__ __forceinline__ void gemm_core(
    const float* __restrict__ A, const float* __restrict__ B,
    int K, int lda, int ldb, int row0, int col0, float acc[4][8][4],
    __nv_bfloat16* gsm)
{
    __nv_bfloat16* sAh = gsm + SM_AH;
    __nv_bfloat16* sAl = gsm + SM_AL;
    __nv_bfloat16* sBh = gsm + SM_BH;
    __nv_bfloat16* sBl = gsm + SM_BL;

    const int tid  = threadIdx.x;          // 0..255
    const int lane = tid & 31;
    const int wm   = (tid >> 5) & 1;       // 0..1 (64 rows each)
    const int wn   = tid >> 6;             // 0..3 (64 cols each)

    const int ar = tid >> 3;               // 0..31
    const int ac = (tid & 7) * 4;

    float4 ra[4], rb[8];

    auto load_tile = [&](int k0) {
        #pragma unroll
        for (int r = 0; r < 4; r++)
            ra[r] = *reinterpret_cast<const float4*>(
                &A[(size_t)(row0 + ar + 32 * r) * lda + k0 + ac]);
        #pragma unroll
        for (int r = 0; r < 8; r++)
            rb[r] = *reinterpret_cast<const float4*>(
                &B[(size_t)(col0 + ar + 32 * r) * ldb + k0 + ac]);
    };

    auto store_tile = [&]() {
        #pragma unroll
        for (int r = 0; r < 4; r++) {
            const int off = (ar + 32 * r) * SAS + ac;
            uint32_t h0, l0, h1, l1;
            split2(ra[r].x, ra[r].y, h0, l0);
            split2(ra[r].z, ra[r].w, h1, l1);
            *reinterpret_cast<uint32_t*>(&sAh[off])     = h0;
            *reinterpret_cast<uint32_t*>(&sAh[off + 2]) = h1;
            *reinterpret_cast<uint32_t*>(&sAl[off])     = l0;
            *reinterpret_cast<uint32_t*>(&sAl[off + 2]) = l1;
        }
        #pragma unroll
        for (int r = 0; r < 8; r++) {
            const int off = (ar + 32 * r) * SAS + ac;
            uint32_t h0, l0, h1, l1;
            split2(rb[r].x, rb[r].y, h0, l0);
            split2(rb[r].z, rb[r].w, h1, l1);
            *reinterpret_cast<uint32_t*>(&sBh[off])     = h0;
            *reinterpret_cast<uint32_t*>(&sBh[off + 2]) = h1;
            *reinterpret_cast<uint32_t*>(&sBl[off])     = l0;
            *reinterpret_cast<uint32_t*>(&sBl[off + 2]) = l1;
        }
    };

    load_tile(0);
    store_tile();
    __syncthreads();

    for (int k0 = 0; k0 < K; k0 += TBK) {
        const bool more = (k0 + TBK) < K;
        if (more) load_tile(k0 + TBK);

        #pragma unroll
        for (int kk = 0; kk < 2; kk++) {
            const int kb = kk * 16 + (lane & 3) * 2;
            uint32_t ah[4][4], al[4][4];
            #pragma unroll
            for (int i = 0; i < 4; i++) {
                const int m = wm * 64 + i * 16 + (lane >> 2);
                ah[i][0] = *reinterpret_cast<const uint32_t*>(&sAh[m * SAS + kb]);
                ah[i][1] = *reinterpret_cast<const uint32_t*>(&sAh[(m + 8) * SAS + kb]);
                ah[i][2] = *reinterpret_cast<const uint32_t*>(&sAh[m * SAS + kb + 8]);
                ah[i][3] = *reinterpret_cast<const uint32_t*>(&sAh[(m + 8) * SAS + kb + 8]);
                al[i][0] = *reinterpret_cast<const uint32_t*>(&sAl[m * SAS + kb]);
                al[i][1] = *reinterpret_cast<const uint32_t*>(&sAl[(m + 8) * SAS + kb]);
                al[i][2] = *reinterpret_cast<const uint32_t*>(&sAl[m * SAS + kb + 8]);
                al[i][3] = *reinterpret_cast<const uint32_t*>(&sAl[(m + 8) * SAS + kb + 8]);
            }
            #pragma unroll
            for (int j = 0; j < 8; j++) {
                const int n = wn * 64 + j * 8 + (lane >> 2);
                const uint32_t bh0 = *reinterpret_cast<const uint32_t*>(&sBh[n * SAS + kb]);
                const uint32_t bh1 = *reinterpret_cast<const uint32_t*>(&sBh[n * SAS + kb + 8]);
                const uint32_t bl0 = *reinterpret_cast<const uint32_t*>(&sBl[n * SAS + kb]);
                const uint32_t bl1 = *reinterpret_cast<const uint32_t*>(&sBl[n * SAS + kb + 8]);
                #pragma unroll
                for (int i = 0; i < 4; i++) {
                    mma_bf16(acc[i][j], ah[i][0], ah[i][1], ah[i][2], ah[i][3], bh0, bh1);
                    mma_bf16(acc[i][j], ah[i][0], ah[i][1], ah[i][2], ah[i][3], bl0, bl1);
                    mma_bf16(acc[i][j], al[i][0], al[i][1], al[i][2], al[i][3], bh0, bh1);
                }
            }
        }
        __syncthreads();
        if (more) {
            store_tile();
            __syncthreads();
        }
    }
}

// ---------------- fused QKV projection: one launch, z selects weight -----------
__global__ void __launch_bounds__(256) qkv_gemm(
    const float* __restrict__ x,
    const float* __restrict__ wq, const float* __restrict__ wk,
    const float* __restrict__ wv,
    float* __restrict__ q, float* __restrict__ k, float* __restrict__ vt)
{
    extern __shared__ __nv_bfloat16 gsm[];
    const int z = blockIdx.z;
    const float* B = (z == 0) ? wq : (z == 1) ? wk : wv;
    const int row0 = blockIdx.y * TBM;
    const int col0 = blockIdx.x * TBN;

    float acc[4][8][4] = {};
    gemm_core(x, B, DM, DM, DM, row0, col0, acc, gsm);

    const int lane = threadIdx.x & 31;
    const int wm   = (threadIdx.x >> 5) & 1;
    const int wn   = threadIdx.x >> 6;

    if (z == 2) {
        const int b = row0 / SS;
        const int s0 = (row0 - b * SS);
        #pragma unroll
        for (int i = 0; i < 4; i++) {
            const int s = s0 + wm * 64 + i * 16 + (lane >> 2);
            #pragma unroll
            for (int j = 0; j < 8; j++) {
                const int cc = col0 + wn * 64 + j * 8 + 2 * (lane & 3);
                const int h  = cc >> 7;          // head within DM
                const int dd = cc & 127;
                float* vp = vt + ((size_t)(b * HH + h) * DH) * SS;
                vp[(size_t)dd * SS + s]           = acc[i][j][0];
                vp[(size_t)(dd + 1) * SS + s]     = acc[i][j][1];
                vp[(size_t)dd * SS + s + 8]       = acc[i][j][2];
                vp[(size_t)(dd + 1) * SS + s + 8] = acc[i][j][3];
            }
        }
    } else {
        float* C = (z == 0) ? q : k;
        #pragma unroll
        for (int i = 0; i < 4; i++) {
            const int r = row0 + wm * 64 + i * 16 + (lane >> 2);
            #pragma unroll
            for (int j = 0; j < 8; j++) {
                const int cc = col0 + wn * 64 + j * 8 + 2 * (lane & 3);
                float2 lo = make_float2(acc[i][j][0], acc[i][j][1]);
                float2 hi = make_float2(acc[i][j][2], acc[i][j][3]);
                *reinterpret_cast<float2*>(&C[(size_t)r * DM + cc]) = lo;
                *reinterpret_cast<float2*>(&C[(size_t)(r + 8) * DM + cc]) = hi;
            }
        }
    }
}

// ---------------- output projection: out = ao @ wo^T ---------------------------
__global__ void __launch_bounds__(256) wo_gemm(
    const float* __restrict__ ao, const float* __restrict__ wo,
    float* __restrict__ out)
{
    extern __shared__ __nv_bfloat16 gsm[];
    const int row0 = blockIdx.y * TBM;
    const int col0 = blockIdx.x * TBN;

    float acc[4][8][4] = {};
    gemm_core(ao, wo, DM, DM, DM, row0, col0, acc, gsm);

    const int lane = threadIdx.x & 31;
    const int wm   = (threadIdx.x >> 5) & 1;
    const int wn   = threadIdx.x >> 6;

    #pragma unroll
    for (int i = 0; i < 4; i++) {
        const int r = row0 + wm * 64 + i * 16 + (lane >> 2);
        #pragma unroll
        for (int j = 0; j < 8; j++) {
            const int cc = col0 + wn * 64 + j * 8 + 2 * (lane & 3);
            float2 lo = make_float2(acc[i][j][0], acc[i][j][1]);
            float2 hi = make_float2(acc[i][j][2], acc[i][j][3]);
            *reinterpret_cast<float2*>(&out[(size_t)r * DM + cc]) = lo;
            *reinterpret_cast<float2*>(&out[(size_t)(r + 8) * DM + cc]) = hi;
        }
    }
}

// ---------------- RMSNorm + RoPE: merged q+k, 4 heads per block ----------------
__global__ void __launch_bounds__(256) rmsnorm_rope_kernel(
    float* __restrict__ qt, float* __restrict__ kt,
    const float* __restrict__ qw, const float* __restrict__ kw,
    const float* __restrict__ freqs)
{
    float* t       = blockIdx.y ? kt : qt;
    const float* w = blockIdx.y ? kw : qw;

    const int grp = threadIdx.x >> 6;        // 0..3
    const int i   = threadIdx.x & 63;        // 0..63
    const int idx = blockIdx.x * 4 + grp;    // b*S*H + s*H + h
    const int s   = (idx / HH) % SS;
    float* v = t + (size_t)idx * DH;

    float x0 = v[i];
    float x1 = v[i + 64];
    float ss = x0 * x0 + x1 * x1;
    #pragma unroll
    for (int o = 16; o > 0; o >>= 1) ss += __shfl_xor_sync(0xffffffffu, ss, o);
    __shared__ float sm[8];
    if ((i & 31) == 0) sm[threadIdx.x >> 5] = ss;
    __syncthreads();
    float total = sm[grp * 2] + sm[grp * 2 + 1];
    float r = rsqrtf(total * (1.0f / 128.0f) + 1e-6f);

    float n0 = x0 * r * w[i];
    float n1 = x1 * r * w[i + 64];

    const float* F = freqs + (size_t)s * 256 + i * 4;
    v[i]      = F[0] * n0 + F[1] * n1;
    v[i + 64] = F[2] * n0 + F[3] * n1;
}

// ---------------- Flash attention (R7, unchanged) ------------------------------
#define FKV 64
#define KST 136
#define VST 72

__global__ void __launch_bounds__(256) flash_kernel(
    const float* __restrict__ q, const float* __restrict__ k,
    const float* __restrict__ vt, float* __restrict__ ao)
{
    extern __shared__ __nv_bfloat16 fsm[];
    __nv_bfloat16* Kh = fsm;
    __nv_bfloat16* Kl = Kh + FKV * KST;
    __nv_bfloat16* Vh = Kl + FKV * KST;
    __nv_bfloat16* Vl = Vh + DH * VST;

    const int tid  = threadIdx.x;
    const int lane = tid & 31;
    const int w    = tid >> 5;
    const int g    = lane >> 2;
    const int t    = lane & 3;
    const int bh   = blockIdx.y;
    const int b    = bh >> 4;
    const int h    = bh & 15;
    const int q0   = blockIdx.x * 128;

    const float* qb  = q  + ((size_t)(b * SS + q0)) * DM + h * DH;
    const float* kb  = k  + (size_t)b * SS * DM + h * DH;
    const float* vb  = vt + (size_t)bh * DH * SS;
    float*       aob = ao + ((size_t)(b * SS + q0)) * DM + h * DH;

    const float scale = 0.08838834764831845f;

    uint32_t qh[8][4], ql[8][4];
    {
        const float* qw = qb + (size_t)(w * 16) * DM;
        #pragma unroll
        for (int kc = 0; kc < 8; kc++) {
            #pragma unroll
            for (int e = 0; e < 4; e++) {
                const int r = g + ((e & 1) ? 8 : 0);
                const int c = kc * 16 + 2 * t + ((e & 2) ? 8 : 0);
                float2 v2 = *reinterpret_cast<const float2*>(&qw[(size_t)r * DM + c]);
                split2(v2.x * scale, v2.y * scale, qh[kc][e], ql[kc][e]);
            }
        }
    }

    float oacc[16][4] = {};
    float m0 = -INFINITY, m1 = -INFINITY, l0 = 0.0f, l1 = 0.0f;

    for (int kv0 = 0; kv0 < SS; kv0 += FKV) {
        __syncthreads();
        {
            const int row = tid >> 3;
            const int cb  = (tid & 7) * 4;
            #pragma unroll
            for (int pr = 0; pr < 2; pr++) {
                const float* src = kb + (size_t)(kv0 + row + 32 * pr) * DM;
                #pragma unroll
                for (int pc = 0; pc < 4; pc++) {
                    const int c = cb + 32 * pc;
                    float4 v4 = *reinterpret_cast<const float4*>(&src[c]);
                    uint32_t h0, lo0, h1, lo1;
                    split2(v4.x, v4.y, h0, lo0);
                    split2(v4.z, v4.w, h1, lo1);
                    const int off = (row + 32 * pr) * KST + c;
                    *reinterpret_cast<uint32_t*>(&Kh[off])     = h0;
                    *reinterpret_cast<uint32_t*>(&Kh[off + 2]) = h1;
                    *reinterpret_cast<uint32_t*>(&Kl[off])     = lo0;
                    *reinterpret_cast<uint32_t*>(&Kl[off + 2]) = lo1;
                }
            }
        }
        {
            const int row = tid >> 3;
            const int cb  = (tid & 7) * 4;
            #pragma unroll
            for (int pr = 0; pr < 4; pr++) {
                const float* src = vb + (size_t)(row + 32 * pr) * SS + kv0;
                #pragma unroll
                for (int pc = 0; pc < 2; pc++) {
                    const int c = cb + 32 * pc;
                    float4 v4 = *reinterpret_cast<const float4*>(&src[c]);
                    uint32_t h0, lo0, h1, lo1;
                    split2(v4.x, v4.y, h0, lo0);
                    split2(v4.z, v4.w, h1, lo1);
                    const int off = (row + 32 * pr) * VST + c;
                    *reinterpret_cast<uint32_t*>(&Vh[off])     = h0;
                    *reinterpret_cast<uint32_t*>(&Vh[off + 2]) = h1;
                    *reinterpret_cast<uint32_t*>(&Vl[off])     = lo0;
                    *reinterpret_cast<uint32_t*>(&Vl[off + 2]) = lo1;
                }
            }
        }
        __syncthreads();

        float sacc[8][4] = {};
        #pragma unroll
        for (int j = 0; j < 8; j++) {
            #pragma unroll
            for (int kc = 0; kc < 8; kc++) {
                const int off = (j * 8 + g) * KST + kc * 16 + 2 * t;
                uint32_t bh0 = *reinterpret_cast<const uint32_t*>(&Kh[off]);
                uint32_t bh1 = *reinterpret_cast<const uint32_t*>(&Kh[off + 8]);
                uint32_t bl0 = *reinterpret_cast<const uint32_t*>(&Kl[off]);
                uint32_t bl1 = *reinterpret_cast<const uint32_t*>(&Kl[off + 8]);
                mma_bf16(sacc[j], qh[kc][0], qh[kc][1], qh[kc][2], qh[kc][3], bh0, bh1);
                mma_bf16(sacc[j], qh[kc][0], qh[kc][1], qh[kc][2], qh[kc][3], bl0, bl1);
                mma_bf16(sacc[j], ql[kc][0], ql[kc][1], ql[kc][2], ql[kc][3], bh0, bh1);
            }
        }

        float mx0 = -INFINITY, mx1 = -INFINITY;
        #pragma unroll
        for (int j = 0; j < 8; j++) {
            mx0 = fmaxf(mx0, fmaxf(sacc[j][0], sacc[j][1]));
            mx1 = fmaxf(mx1, fmaxf(sacc[j][2], sacc[j][3]));
        }
        mx0 = fmaxf(mx0, __shfl_xor_sync(0xffffffffu, mx0, 1));
        mx0 = fmaxf(mx0, __shfl_xor_sync(0xffffffffu, mx0, 2));
        mx1 = fmaxf(mx1, __shfl_xor_sync(0xffffffffu, mx1, 1));
        mx1 = fmaxf(mx1, __shfl_xor_sync(0xffffffffu, mx1, 2));

        const float nm0 = fmaxf(m0, mx0), nm1 = fmaxf(m1, mx1);
        const float al0 = __expf(m0 - nm0), al1 = __expf(m1 - nm1);
        m0 = nm0; m1 = nm1;

        float s0 = 0.0f, s1 = 0.0f;
        #pragma unroll
        for (int j = 0; j < 8; j++) {
            sacc[j][0] = __expf(sacc[j][0] - nm0);
            sacc[j][1] = __expf(sacc[j][1] - nm0);
            sacc[j][2] = __expf(sacc[j][2] - nm1);
            sacc[j][3] = __expf(sacc[j][3] - nm1);
            s0 += sacc[j][0] + sacc[j][1];
            s1 += sacc[j][2] + sacc[j][3];
        }
        s0 += __shfl_xor_sync(0xffffffffu, s0, 1);
        s0 += __shfl_xor_sync(0xffffffffu, s0, 2);
        s1 += __shfl_xor_sync(0xffffffffu, s1, 1);
        s1 += __shfl_xor_sync(0xffffffffu, s1, 2);
        l0 = l0 * al0 + s0;
        l1 = l1 * al1 + s1;

        #pragma unroll
        for (int jn = 0; jn < 16; jn++) {
            oacc[jn][0] *= al0; oacc[jn][1] *= al0;
            oacc[jn][2] *= al1; oacc[jn][3] *= al1;
        }

        #pragma unroll
        for (int kc2 = 0; kc2 < 4; kc2++) {
            const int j0 = 2 * kc2, j1 = 2 * kc2 + 1;
            uint32_t pa0h, pa0l, pa1h, pa1l, pa2h, pa2l, pa3h, pa3l;
            split2(sacc[j0][0], sacc[j0][1], pa0h, pa0l);
            split2(sacc[j0][2], sacc[j0][3], pa1h, pa1l);
            split2(sacc[j1][0], sacc[j1][1], pa2h, pa2l);
            split2(sacc[j1][2], sacc[j1][3], pa3h, pa3l);
            #pragma unroll
            for (int jn = 0; jn < 16; jn++) {
                const int off = (jn * 8 + g) * VST + kc2 * 16 + 2 * t;
                uint32_t bh0 = *reinterpret_cast<const uint32_t*>(&Vh[off]);
                uint32_t bh1 = *reinterpret_cast<const uint32_t*>(&Vh[off + 8]);
                uint32_t bl0 = *reinterpret_cast<const uint32_t*>(&Vl[off]);
                uint32_t bl1 = *reinterpret_cast<const uint32_t*>(&Vl[off + 8]);
                mma_bf16(oacc[jn], pa0h, pa1h, pa2h, pa3h, bh0, bh1);
                mma_bf16(oacc[jn], pa0h, pa1h, pa2h, pa3h, bl0, bl1);
                mma_bf16(oacc[jn], pa0l, pa1l, pa2l, pa3l, bh0, bh1);
            }
        }
    }

    const float inv0 = 1.0f / l0, inv1 = 1.0f / l1;
    #pragma unroll
    for (int jn = 0; jn < 16; jn++) {
        const int r = w * 16 + g;
        const int c = jn * 8 + 2 * t;
        float2 lo = make_float2(oacc[jn][0] * inv0, oacc[jn][1] * inv0);
        float2 hi = make_float2(oacc[jn][2] * inv1, oacc[jn][3] * inv1);
        *reinterpret_cast<float2*>(&aob[(size_t)r * DM + c])       = lo;
        *reinterpret_cast<float2*>(&aob[(size_t)(r + 8) * DM + c]) = hi;
    }
}

// ---------------- launch -------------------------------------------------------
extern "C" void kernel_launch(void* const* d_in, const int* in_sizes, int n_in,
                              void* d_out, int out_size)
{
    const float* x     = (const float*)d_in[0];
    const float* rope  = (const float*)d_in[1];
    const float* wq    = (const float*)d_in[2];
    const float* wk    = (const float*)d_in[3];
    const float* wv    = (const float*)d_in[4];
    const float* wo    = (const float*)d_in[5];
    const float* qnw   = (const float*)d_in[6];
    const float* knw   = (const float*)d_in[7];
    float* out = (float*)d_out;

    float *q, *k, *vt, *ao;
    cudaGetSymbolAddress((void**)&q,  g_q);
    cudaGetSymbolAddress((void**)&k,  g_k);
    cudaGetSymbolAddress((void**)&vt, g_v);
    cudaGetSymbolAddress((void**)&ao, g_ao);

    cudaFuncSetAttribute(qkv_gemm, cudaFuncAttributeMaxDynamicSharedMemorySize, GEMM_SMEM);
    cudaFuncSetAttribute(wo_gemm,  cudaFuncAttributeMaxDynamicSharedMemorySize, GEMM_SMEM);
    cudaFuncSetAttribute(flash_kernel, cudaFuncAttributeMaxDynamicSharedMemorySize, 71680);

    // ---- QKV projections: ONE launch, z selects weight/output ----------------
    qkv_gemm<<<dim3(DM / TBN, MROWS / TBM, 3), 256, GEMM_SMEM>>>(x, wq, wk, wv, q, k, vt);

    // ---- RMSNorm + RoPE on q and k: one merged launch -------------------------
    rmsnorm_rope_kernel<<<dim3(MROWS * HH / 4, 2), 256>>>(q, k, qnw, knw, rope);

    // ---- fused attention ------------------------------------------------------
    flash_kernel<<<dim3(SS / 128, NBH), 256, 71680>>>(q, k, vt, ao);

    // ---- output projection ----------------------------------------------------
    wo_gemm<<<dim3(DM / TBN, MROWS / TBM), 256, GEMM_SMEM>>>(ao, wo, out);
}